// round 13
// baseline (speedup 1.0000x reference)
#include <cuda_runtime.h>
#include <cuda_bf16.h>
#include <cstdint>

// Problem dims (fixed by the reference)
#define BB   8
#define TT   4096
#define CC   256
#define NC   64           // chunks along T for the parallel WKV scan
#define LCH  (TT / NC)    // 64 steps per chunk
#define INV_T (1.0f / 4096.0f)
#define INV_C (1.0f / 256.0f)
#define NTOT (BB * TT * CC)

// ---------------- scratch (static __device__ — no allocations allowed) -----
__device__ float g_k [NTOT];
__device__ float g_v [NTOT];
__device__ float g_sr[NTOT];           // sigmoid(r) fp32
__device__ float g_rp[BB * NC * CC];
__device__ float g_rq[BB * NC * CC];
__device__ float g_ro[BB * NC * CC];
__device__ float g_pp[BB * NC * CC];
__device__ float g_pq[BB * NC * CC];
__device__ float g_po[BB * NC * CC];

// bf16 hi/lo split activations (A operands for the GEMMs)
__device__ __align__(16) __nv_bfloat16 g_xhi[NTOT];
__device__ __align__(16) __nv_bfloat16 g_xlo[NTOT];
__device__ __align__(16) __nv_bfloat16 g_zhi[NTOT];   // z = sigmoid(r)*LN(y)
__device__ __align__(16) __nv_bfloat16 g_zlo[NTOT];

// bf16 hi/lo split weights, [w][n=256][k=256] row-major, packed as uint32 (2 bf16)
__device__ __align__(16) uint32_t g_whi[4 * 256 * 128];   // 512 KB
__device__ __align__(16) uint32_t g_wlo[4 * 256 * 128];   // 512 KB

// ---------------------------------------------------------------------------
// helpers
// ---------------------------------------------------------------------------
__device__ __forceinline__ uint32_t smem_u32(const void* p) {
    uint32_t a;
    asm("{ .reg .u64 t; cvta.to.shared.u64 t, %1; cvt.u32.u64 %0, t; }"
        : "=r"(a) : "l"(p));
    return a;
}

// split a pair of fp32 into packed bf16 hi and bf16 lo words
__device__ __forceinline__ void split2(float a, float b, uint32_t& h, uint32_t& l) {
    __nv_bfloat16 ha = __float2bfloat16_rn(a);
    __nv_bfloat16 hb = __float2bfloat16_rn(b);
    __nv_bfloat16 la = __float2bfloat16_rn(a - __bfloat162float(ha));
    __nv_bfloat16 lb = __float2bfloat16_rn(b - __bfloat162float(hb));
    h = ((uint32_t)__bfloat16_as_ushort(hb) << 16) | __bfloat16_as_ushort(ha);
    l = ((uint32_t)__bfloat16_as_ushort(lb) << 16) | __bfloat16_as_ushort(la);
}

__device__ __forceinline__ void ldmx4(uint32_t* r, uint32_t addr) {
    asm volatile("ldmatrix.sync.aligned.m8n8.x4.shared.b16 {%0,%1,%2,%3}, [%4];"
                 : "=r"(r[0]), "=r"(r[1]), "=r"(r[2]), "=r"(r[3]) : "r"(addr));
}
__device__ __forceinline__ void ldmx2(uint32_t* r, uint32_t addr) {
    asm volatile("ldmatrix.sync.aligned.m8n8.x2.shared.b16 {%0,%1}, [%2];"
                 : "=r"(r[0]), "=r"(r[1]) : "r"(addr));
}
__device__ __forceinline__ void mma16816(float* d, const uint32_t* a, const uint32_t* b) {
    asm volatile(
        "mma.sync.aligned.m16n8k16.row.col.f32.bf16.bf16.f32 "
        "{%0,%1,%2,%3}, {%4,%5,%6,%7}, {%8,%9}, {%0,%1,%2,%3};"
        : "+f"(d[0]), "+f"(d[1]), "+f"(d[2]), "+f"(d[3])
        : "r"(a[0]), "r"(a[1]), "r"(a[2]), "r"(a[3]), "r"(b[0]), "r"(b[1]));
}
__device__ __forceinline__ void cp16(uint32_t saddr, const void* g) {
    asm volatile("cp.async.cg.shared.global [%0], [%1], 16;"
                 :: "r"(saddr), "l"(g) : "memory");
}
__device__ __forceinline__ void cp_commit() {
    asm volatile("cp.async.commit_group;" ::: "memory");
}

// ---------------------------------------------------------------------------
// Weight prep: fp32 [256,256] -> bf16 hi/lo packed pairs at [w][n][k/2]
// ---------------------------------------------------------------------------
__global__ __launch_bounds__(256)
void prep_w_kernel(const float* __restrict__ Wk, const float* __restrict__ Wv,
                   const float* __restrict__ Wr, const float* __restrict__ Wo)
{
    int gid = blockIdx.x * 256 + threadIdx.x;    // 0 .. 131071 = 4*256*128
    int kp  = gid & 127;
    int n   = (gid >> 7) & 255;
    int w   = gid >> 15;
    const float* W = (w == 0) ? Wk : (w == 1) ? Wv : (w == 2) ? Wr : Wo;
    float2 v = *(const float2*)(W + n * 256 + kp * 2);
    uint32_t h, l;
    split2(v.x, v.y, h, l);
    g_whi[gid] = h;
    g_wlo[gid] = l;
}

// x fp32 -> bf16 hi/lo (one pass, so GEMM staging is a pure async copy)
__global__ __launch_bounds__(256)
void prep_x_kernel(const float* __restrict__ x)
{
    int gid = blockIdx.x * 256 + threadIdx.x;   // < NTOT/2
    float2 v = *(const float2*)(x + (size_t)gid * 2);
    uint32_t h, l;
    split2(v.x, v.y, h, l);
    ((uint32_t*)g_xhi)[gid] = h;
    ((uint32_t*)g_xlo)[gid] = l;
}

// ---------------------------------------------------------------------------
// Split-bf16 tensor-core GEMM (NT) via cp.async + ldmatrix + mma.sync.
// O[m,n] = sum_c A[m,c] * W[n,c].  CTA tile 128x128, BK=32, 8 warps (2m x 4n),
// fp32 accum, 3 MMA terms: Ahi*Whi + Ahi*Wlo + Alo*Whi.
// 2-stage cp.async double buffer: loads for kc+1 overlap MMA of kc.
// ---------------------------------------------------------------------------
#define PITCH 80                 // smem row pitch: 64 B data + 16 B pad
#define TBYTES (128 * PITCH)     // 10240 per tile
#define STG    (4 * TBYTES)      // 40960 per stage (Ahi,Alo,Whi,Wlo)
#define SMEM_BYTES (2 * STG)     // 81920

__device__ __forceinline__ void gemm_mma_body(
    const __nv_bfloat16* __restrict__ Ahi, const __nv_bfloat16* __restrict__ Alo,
    int w_sel, float* __restrict__ O, int m0, int n0, int do_sig)
{
    extern __shared__ __align__(16) unsigned char smem[];
    const uint32_t base = smem_u32(smem);

    const int tid  = threadIdx.x;
    const int wid  = tid >> 5;
    const int lane = tid & 31;
    const int wm   = wid & 1;        // 0..1 : 64-row half
    const int wn   = wid >> 1;       // 0..3 : 32-col quarter

    const uint32_t aOff = (uint32_t)((wm * 64 + (lane & 15)) * PITCH + (lane >> 4) * 16);
    const uint32_t bOff = (uint32_t)((wn * 32 + (lane & 7)) * PITCH + ((lane >> 3) & 1) * 16);

    float acc[4][4][4];
#pragma unroll
    for (int i = 0; i < 4; i++)
#pragma unroll
        for (int j = 0; j < 4; j++)
#pragma unroll
            for (int e = 0; e < 4; e++) acc[i][j][e] = 0.f;

    const int arow  = tid >> 1;      // each thread stages half a row (32 B) per tile
    const int ahalf = tid & 1;

    const __nv_bfloat16* pAh = Ahi + (size_t)(m0 + arow) * CC + ahalf * 16;
    const __nv_bfloat16* pAl = Alo + (size_t)(m0 + arow) * CC + ahalf * 16;
    const uint32_t* pWh = g_whi + (w_sel * 256 + n0 + arow) * 128 + ahalf * 8;
    const uint32_t* pWl = g_wlo + (w_sel * 256 + n0 + arow) * 128 + ahalf * 8;
    const uint32_t sOff = (uint32_t)(arow * PITCH + ahalf * 32);

    // stage loader for K-chunk kc into stage s
#define STAGE_LOAD(kc, s) do { \
        uint32_t so = base + (s) * STG + sOff; \
        cp16(so,                    pAh + (kc) * 32); \
        cp16(so + 16,               pAh + (kc) * 32 + 8); \
        cp16(so + TBYTES,           pAl + (kc) * 32); \
        cp16(so + TBYTES + 16,      pAl + (kc) * 32 + 8); \
        cp16(so + 2 * TBYTES,       pWh + (kc) * 16); \
        cp16(so + 2 * TBYTES + 16,  pWh + (kc) * 16 + 4); \
        cp16(so + 3 * TBYTES,       pWl + (kc) * 16); \
        cp16(so + 3 * TBYTES + 16,  pWl + (kc) * 16 + 4); \
        cp_commit(); \
    } while (0)

    STAGE_LOAD(0, 0);

    for (int kc = 0; kc < 8; kc++) {
        if (kc < 7) STAGE_LOAD(kc + 1, (kc + 1) & 1);
        if (kc < 7) asm volatile("cp.async.wait_group 1;" ::: "memory");
        else        asm volatile("cp.async.wait_group 0;" ::: "memory");
        __syncthreads();

        const uint32_t sb   = base + (kc & 1) * STG;
        const uint32_t uAhi = sb;
        const uint32_t uAlo = sb + TBYTES;
        const uint32_t uWhi = sb + 2 * TBYTES;
        const uint32_t uWlo = sb + 3 * TBYTES;

#pragma unroll
        for (int kk = 0; kk < 2; kk++) {
            uint32_t bh[4][2], bl[4][2];
#pragma unroll
            for (int j = 0; j < 4; j++) {
                uint32_t off = bOff + (uint32_t)(j * 8 * PITCH + kk * 32);
                ldmx2(bh[j], uWhi + off);
                ldmx2(bl[j], uWlo + off);
            }
#pragma unroll
            for (int i = 0; i < 4; i++) {
                uint32_t off = aOff + (uint32_t)(i * 16 * PITCH + kk * 32);
                uint32_t ah[4], al[4];
                ldmx4(ah, uAhi + off);
                ldmx4(al, uAlo + off);
#pragma unroll
                for (int j = 0; j < 4; j++) {
                    mma16816(acc[i][j], ah, bh[j]);
                    mma16816(acc[i][j], ah, bl[j]);
                    mma16816(acc[i][j], al, bh[j]);
                }
            }
        }
        __syncthreads();
    }
#undef STAGE_LOAD

    // --- epilogue: fragments -> global fp32 ---
    const int r0 = m0 + wm * 64 + (lane >> 2);
    const int c0 = n0 + wn * 32 + (lane & 3) * 2;
#pragma unroll
    for (int i = 0; i < 4; i++) {
#pragma unroll
        for (int j = 0; j < 4; j++) {
            float v0 = acc[i][j][0], v1 = acc[i][j][1];
            float v2 = acc[i][j][2], v3 = acc[i][j][3];
            if (do_sig) {
                v0 = __fdividef(1.f, 1.f + __expf(-v0));
                v1 = __fdividef(1.f, 1.f + __expf(-v1));
                v2 = __fdividef(1.f, 1.f + __expf(-v2));
                v3 = __fdividef(1.f, 1.f + __expf(-v3));
            }
            float* p = O + (size_t)(r0 + i * 16) * CC + c0 + j * 8;
            *(float2*)p              = make_float2(v0, v1);
            *(float2*)(p + 8 * CC)   = make_float2(v2, v3);
        }
    }
}

__global__ __launch_bounds__(256)
void gemm_kvr_mma()
{
    const int w     = blockIdx.x >> 1;        // 0:k 1:v 2:r
    const int ntile = blockIdx.x & 1;
    float* O = (w == 0) ? g_k : (w == 1) ? g_v : g_sr;
    gemm_mma_body(g_xhi, g_xlo, w, O, blockIdx.y * 128, ntile * 128, w == 2);
}

__global__ __launch_bounds__(256)
void gemm_out_mma(float* __restrict__ out)
{
    gemm_mma_body(g_zhi, g_zlo, 3, out, blockIdx.y * 128, (blockIdx.x & 1) * 128, 0);
}

// ---------------------------------------------------------------------------
// WKV pass 1: per (b, chunk) state recurrence from identity; 2 chains/thread.
// ---------------------------------------------------------------------------
__global__ __launch_bounds__(256)
void wkv_pass1_kernel(const float* __restrict__ decay)
{
    const int c  = threadIdx.x;
    const int j0 = blockIdx.x * 2;
    const int b  = blockIdx.y;
    const float w = decay[c] * INV_T;
    float p0 = 0.f, q0 = 0.f, o0 = -1e38f;
    float p1 = 0.f, q1 = 0.f, o1 = -1e38f;
    int idx0 = (b * TT + j0 * LCH) * CC + c;
    int idx1 = idx0 + LCH * CC;
#pragma unroll 4
    for (int t = 0; t < LCH; t++, idx0 += CC, idx1 += CC) {
        float k0 = g_k[idx0], v0 = g_v[idx0];
        float k1 = g_k[idx1], v1 = g_v[idx1];
        float n0 = fmaxf(w + o0, k0);
        float n1 = fmaxf(w + o1, k1);
        float a0 = __expf(w + o0 - n0), b0 = __expf(k0 - n0);
        float a1 = __expf(w + o1 - n1), b1 = __expf(k1 - n1);
        p0 = a0 * p0 + b0 * v0;  q0 = a0 * q0 + b0;  o0 = n0;
        p1 = a1 * p1 + b1 * v1;  q1 = a1 * q1 + b1;  o1 = n1;
    }
    int s0 = (b * NC + j0) * CC + c;
    g_rp[s0] = p0; g_rq[s0] = q0; g_ro[s0] = o0;
    int s1 = s0 + CC;
    g_rp[s1] = p1; g_rq[s1] = q1; g_ro[s1] = o1;
}

// ---------------------------------------------------------------------------
// WKV pass 2: sequential combine across chunk summaries per (b,c), batched 8.
// ---------------------------------------------------------------------------
__global__ __launch_bounds__(256)
void wkv_pass2_kernel(const float* __restrict__ decay)
{
    const int c = threadIdx.x;
    const int b = blockIdx.x;
    const float Lw = decay[c] * INV_T * (float)LCH;
    float p = 0.f, q = 0.f, o = -1e38f;
    for (int j0 = 0; j0 < NC; j0 += 8) {
        float rp8[8], rq8[8], ro8[8];
#pragma unroll
        for (int u = 0; u < 8; u++) {
            const int s = (b * NC + j0 + u) * CC + c;
            rp8[u] = g_rp[s]; rq8[u] = g_rq[s]; ro8[u] = g_ro[s];
        }
#pragma unroll
        for (int u = 0; u < 8; u++) {
            const int s = (b * NC + j0 + u) * CC + c;
            g_pp[s] = p; g_pq[s] = q; g_po[s] = o;
            float so = o + Lw;
            float no = fmaxf(so, ro8[u]);
            float ea = __expf(so - no);
            float eb = __expf(ro8[u] - no);
            p = ea * p + eb * rp8[u];
            q = ea * q + eb * rq8[u];
            o = no;
        }
    }
}

// ---------------------------------------------------------------------------
// WKV pass 3: replay chunk, fuse LayerNorm + sigmoid gate; write z as
// bf16 hi/lo (GEMM-ready).  LN reduction batched over 8 timesteps.
// ---------------------------------------------------------------------------
__global__ __launch_bounds__(256)
void wkv_pass3_kernel(const float* __restrict__ decay,
                      const float* __restrict__ first,
                      const float* __restrict__ ln_w,
                      const float* __restrict__ ln_b)
{
    __shared__ float sh_s [8][8];   // [t-sub][warp]
    __shared__ float sh_s2[8][8];
    const int c = threadIdx.x;
    const int j = blockIdx.x;
    const int b = blockIdx.y;
    const int wid  = c >> 5;
    const int lane = c & 31;

    const float w = decay[c] * INV_T;
    const float u = first[c] * INV_T;
    const float lw = ln_w[c], lb = ln_b[c];

    const int s = (b * NC + j) * CC + c;
    float p = g_pp[s], q = g_pq[s], o = g_po[s];

    int idx = (b * TT + j * LCH) * CC + c;
    for (int tb = 0; tb < LCH; tb += 8) {
        float yb[8];
        int idx2 = idx;
#pragma unroll
        for (int tt = 0; tt < 8; tt++, idx += CC) {
            float kt = g_k[idx], vt = g_v[idx];

            float no = fmaxf(o, u + kt);
            float ea = __expf(o - no);
            float eb = __expf(u + kt - no);
            float y  = __fdividef(ea * p + eb * vt, ea * q + eb);
            yb[tt] = y;

            float no2 = fmaxf(w + o, kt);
            float e2  = __expf(w + o - no2);
            float e3  = __expf(kt - no2);
            p = e2 * p + e3 * vt;
            q = e2 * q + e3;
            o = no2;

            float sv = y, sv2 = y * y;
#pragma unroll
            for (int off = 16; off; off >>= 1) {
                sv  += __shfl_xor_sync(0xffffffffu, sv,  off);
                sv2 += __shfl_xor_sync(0xffffffffu, sv2, off);
            }
            if (lane == 0) { sh_s[tt][wid] = sv; sh_s2[tt][wid] = sv2; }
        }
        __syncthreads();
#pragma unroll
        for (int tt = 0; tt < 8; tt++, idx2 += CC) {
            float mean = 0.f, msq = 0.f;
#pragma unroll
            for (int i = 0; i < 8; i++) { mean += sh_s[tt][i]; msq += sh_s2[tt][i]; }
            mean *= INV_C;
            float var = msq * INV_C - mean * mean;
            float inv = rsqrtf(var + 1e-5f);
            float z = (yb[tt] - mean) * inv * lw + lb;
            float zz = z * g_sr[idx2];
            __nv_bfloat16 zh = __float2bfloat16_rn(zz);
            __nv_bfloat16 zl = __float2bfloat16_rn(zz - __bfloat162float(zh));
            g_zhi[idx2] = zh;
            g_zlo[idx2] = zl;
        }
        __syncthreads();
    }
}

// ---------------------------------------------------------------------------
extern "C" void kernel_launch(void* const* d_in, const int* in_sizes, int n_in,
                              void* d_out, int out_size)
{
    const float* x     = (const float*)d_in[0];
    const float* Wk    = (const float*)d_in[1];
    const float* Wv    = (const float*)d_in[2];
    const float* Wr    = (const float*)d_in[3];
    const float* Wo    = (const float*)d_in[4];
    const float* decay = (const float*)d_in[5];
    const float* first = (const float*)d_in[6];
    const float* ln_w  = (const float*)d_in[7];
    const float* ln_b  = (const float*)d_in[8];
    float* out = (float*)d_out;

    // host-side attribute set (not a stream op; legal during capture)
    cudaFuncSetAttribute(gemm_kvr_mma, cudaFuncAttributeMaxDynamicSharedMemorySize, SMEM_BYTES);
    cudaFuncSetAttribute(gemm_out_mma, cudaFuncAttributeMaxDynamicSharedMemorySize, SMEM_BYTES);

    const int MT = (BB * TT) / 128;   // 256 m-tiles

    prep_w_kernel<<<512, 256>>>(Wk, Wv, Wr, Wo);
    prep_x_kernel<<<NTOT / 512, 256>>>(x);
    gemm_kvr_mma<<<dim3(6, MT), 256, SMEM_BYTES>>>();
    wkv_pass1_kernel<<<dim3(NC / 2, BB), 256>>>(decay);
    wkv_pass2_kernel<<<BB, 256>>>(decay);
    wkv_pass3_kernel<<<dim3(NC, BB), 256>>>(decay, first, ln_w, ln_b);
    gemm_out_mma<<<dim3(2, MT), 256, SMEM_BYTES>>>(out);
}

// round 14
// speedup vs baseline: 1.0022x; 1.0022x over previous
#include <cuda_runtime.h>
#include <cuda_bf16.h>
#include <cstdint>

// Problem dims (fixed by the reference)
#define BB   8
#define TT   4096
#define CC   256
#define NC   64           // chunks along T for the parallel WKV scan
#define LCH  (TT / NC)    // 64 steps per chunk
#define INV_T (1.0f / 4096.0f)
#define INV_C (1.0f / 256.0f)
#define NTOT (BB * TT * CC)

// ---------------- scratch (static __device__ — no allocations allowed) -----
__device__ float g_k [NTOT];
__device__ float g_v [NTOT];
__device__ float g_sr[NTOT];           // sigmoid(r) fp32
__device__ float g_rp[BB * NC * CC];
__device__ float g_rq[BB * NC * CC];
__device__ float g_ro[BB * NC * CC];
__device__ float g_pp[BB * NC * CC];
__device__ float g_pq[BB * NC * CC];
__device__ float g_po[BB * NC * CC];

// bf16 hi/lo split activations (A operands for the GEMMs)
__device__ __align__(16) __nv_bfloat16 g_xhi[NTOT];
__device__ __align__(16) __nv_bfloat16 g_xlo[NTOT];
__device__ __align__(16) __nv_bfloat16 g_zhi[NTOT];   // z = sigmoid(r)*LN(y)
__device__ __align__(16) __nv_bfloat16 g_zlo[NTOT];

// bf16 hi/lo split weights, [w][n=256][k=256] row-major, packed as uint32 (2 bf16)
__device__ __align__(16) uint32_t g_whi[4 * 256 * 128];   // 512 KB
__device__ __align__(16) uint32_t g_wlo[4 * 256 * 128];   // 512 KB

// ---------------------------------------------------------------------------
// helpers
// ---------------------------------------------------------------------------
__device__ __forceinline__ uint32_t smem_u32(const void* p) {
    uint32_t a;
    asm("{ .reg .u64 t; cvta.to.shared.u64 t, %1; cvt.u32.u64 %0, t; }"
        : "=r"(a) : "l"(p));
    return a;
}

// split a pair of fp32 into packed bf16 hi and bf16 lo words
__device__ __forceinline__ void split2(float a, float b, uint32_t& h, uint32_t& l) {
    __nv_bfloat16 ha = __float2bfloat16_rn(a);
    __nv_bfloat16 hb = __float2bfloat16_rn(b);
    __nv_bfloat16 la = __float2bfloat16_rn(a - __bfloat162float(ha));
    __nv_bfloat16 lb = __float2bfloat16_rn(b - __bfloat162float(hb));
    h = ((uint32_t)__bfloat16_as_ushort(hb) << 16) | __bfloat16_as_ushort(ha);
    l = ((uint32_t)__bfloat16_as_ushort(lb) << 16) | __bfloat16_as_ushort(la);
}

__device__ __forceinline__ void ldmx4(uint32_t* r, uint32_t addr) {
    asm volatile("ldmatrix.sync.aligned.m8n8.x4.shared.b16 {%0,%1,%2,%3}, [%4];"
                 : "=r"(r[0]), "=r"(r[1]), "=r"(r[2]), "=r"(r[3]) : "r"(addr));
}
__device__ __forceinline__ void ldmx2(uint32_t* r, uint32_t addr) {
    asm volatile("ldmatrix.sync.aligned.m8n8.x2.shared.b16 {%0,%1}, [%2];"
                 : "=r"(r[0]), "=r"(r[1]) : "r"(addr));
}
__device__ __forceinline__ void mma16816(float* d, const uint32_t* a, const uint32_t* b) {
    asm volatile(
        "mma.sync.aligned.m16n8k16.row.col.f32.bf16.bf16.f32 "
        "{%0,%1,%2,%3}, {%4,%5,%6,%7}, {%8,%9}, {%0,%1,%2,%3};"
        : "+f"(d[0]), "+f"(d[1]), "+f"(d[2]), "+f"(d[3])
        : "r"(a[0]), "r"(a[1]), "r"(a[2]), "r"(a[3]), "r"(b[0]), "r"(b[1]));
}
__device__ __forceinline__ void cp16(uint32_t saddr, const void* g) {
    asm volatile("cp.async.cg.shared.global [%0], [%1], 16;"
                 :: "r"(saddr), "l"(g) : "memory");
}
__device__ __forceinline__ void cp_commit() {
    asm volatile("cp.async.commit_group;" ::: "memory");
}

// ---------------------------------------------------------------------------
// Weight prep: fp32 [256,256] -> bf16 hi/lo packed pairs at [w][n][k/2]
// ---------------------------------------------------------------------------
__global__ __launch_bounds__(256)
void prep_w_kernel(const float* __restrict__ Wk, const float* __restrict__ Wv,
                   const float* __restrict__ Wr, const float* __restrict__ Wo)
{
    int gid = blockIdx.x * 256 + threadIdx.x;    // 0 .. 131071 = 4*256*128
    int kp  = gid & 127;
    int n   = (gid >> 7) & 255;
    int w   = gid >> 15;
    const float* W = (w == 0) ? Wk : (w == 1) ? Wv : (w == 2) ? Wr : Wo;
    float2 v = *(const float2*)(W + n * 256 + kp * 2);
    uint32_t h, l;
    split2(v.x, v.y, h, l);
    g_whi[gid] = h;
    g_wlo[gid] = l;
}

// x fp32 -> bf16 hi/lo (one pass, so GEMM staging is a pure async copy)
__global__ __launch_bounds__(256)
void prep_x_kernel(const float* __restrict__ x)
{
    int gid = blockIdx.x * 256 + threadIdx.x;   // < NTOT/2
    float2 v = *(const float2*)(x + (size_t)gid * 2);
    uint32_t h, l;
    split2(v.x, v.y, h, l);
    ((uint32_t*)g_xhi)[gid] = h;
    ((uint32_t*)g_xlo)[gid] = l;
}

// ---------------------------------------------------------------------------
// Split-bf16 tensor-core GEMM (NT) via cp.async + ldmatrix + mma.sync.
// O[m,n] = sum_c A[m,c] * W[n,c].  CTA tile 128x128, BK=32, 8 warps (2m x 4n),
// fp32 accum, 3 MMA terms: Ahi*Whi + Ahi*Wlo + Alo*Whi.
// 2-stage cp.async double buffer: loads for kc+1 overlap MMA of kc.
// ---------------------------------------------------------------------------
#define PITCH 80                 // smem row pitch: 64 B data + 16 B pad
#define TBYTES (128 * PITCH)     // 10240 per tile
#define STG    (4 * TBYTES)      // 40960 per stage (Ahi,Alo,Whi,Wlo)
#define SMEM_BYTES (2 * STG)     // 81920

__device__ __forceinline__ void gemm_mma_body(
    const __nv_bfloat16* __restrict__ Ahi, const __nv_bfloat16* __restrict__ Alo,
    int w_sel, float* __restrict__ O, int m0, int n0, int do_sig)
{
    extern __shared__ __align__(16) unsigned char smem[];
    const uint32_t base = smem_u32(smem);

    const int tid  = threadIdx.x;
    const int wid  = tid >> 5;
    const int lane = tid & 31;
    const int wm   = wid & 1;        // 0..1 : 64-row half
    const int wn   = wid >> 1;       // 0..3 : 32-col quarter

    const uint32_t aOff = (uint32_t)((wm * 64 + (lane & 15)) * PITCH + (lane >> 4) * 16);
    const uint32_t bOff = (uint32_t)((wn * 32 + (lane & 7)) * PITCH + ((lane >> 3) & 1) * 16);

    float acc[4][4][4];
#pragma unroll
    for (int i = 0; i < 4; i++)
#pragma unroll
        for (int j = 0; j < 4; j++)
#pragma unroll
            for (int e = 0; e < 4; e++) acc[i][j][e] = 0.f;

    const int arow  = tid >> 1;      // each thread stages half a row (32 B) per tile
    const int ahalf = tid & 1;

    const __nv_bfloat16* pAh = Ahi + (size_t)(m0 + arow) * CC + ahalf * 16;
    const __nv_bfloat16* pAl = Alo + (size_t)(m0 + arow) * CC + ahalf * 16;
    const uint32_t* pWh = g_whi + (w_sel * 256 + n0 + arow) * 128 + ahalf * 8;
    const uint32_t* pWl = g_wlo + (w_sel * 256 + n0 + arow) * 128 + ahalf * 8;
    const uint32_t sOff = (uint32_t)(arow * PITCH + ahalf * 32);

    // stage loader for K-chunk kc into stage s
#define STAGE_LOAD(kc, s) do { \
        uint32_t so = base + (s) * STG + sOff; \
        cp16(so,                    pAh + (kc) * 32); \
        cp16(so + 16,               pAh + (kc) * 32 + 8); \
        cp16(so + TBYTES,           pAl + (kc) * 32); \
        cp16(so + TBYTES + 16,      pAl + (kc) * 32 + 8); \
        cp16(so + 2 * TBYTES,       pWh + (kc) * 16); \
        cp16(so + 2 * TBYTES + 16,  pWh + (kc) * 16 + 4); \
        cp16(so + 3 * TBYTES,       pWl + (kc) * 16); \
        cp16(so + 3 * TBYTES + 16,  pWl + (kc) * 16 + 4); \
        cp_commit(); \
    } while (0)

    STAGE_LOAD(0, 0);

    for (int kc = 0; kc < 8; kc++) {
        if (kc < 7) STAGE_LOAD(kc + 1, (kc + 1) & 1);
        if (kc < 7) asm volatile("cp.async.wait_group 1;" ::: "memory");
        else        asm volatile("cp.async.wait_group 0;" ::: "memory");
        __syncthreads();

        const uint32_t sb   = base + (kc & 1) * STG;
        const uint32_t uAhi = sb;
        const uint32_t uAlo = sb + TBYTES;
        const uint32_t uWhi = sb + 2 * TBYTES;
        const uint32_t uWlo = sb + 3 * TBYTES;

#pragma unroll
        for (int kk = 0; kk < 2; kk++) {
            uint32_t bh[4][2], bl[4][2];
#pragma unroll
            for (int j = 0; j < 4; j++) {
                uint32_t off = bOff + (uint32_t)(j * 8 * PITCH + kk * 32);
                ldmx2(bh[j], uWhi + off);
                ldmx2(bl[j], uWlo + off);
            }
#pragma unroll
            for (int i = 0; i < 4; i++) {
                uint32_t off = aOff + (uint32_t)(i * 16 * PITCH + kk * 32);
                uint32_t ah[4], al[4];
                ldmx4(ah, uAhi + off);
                ldmx4(al, uAlo + off);
#pragma unroll
                for (int j = 0; j < 4; j++) {
                    mma16816(acc[i][j], ah, bh[j]);
                    mma16816(acc[i][j], ah, bl[j]);
                    mma16816(acc[i][j], al, bh[j]);
                }
            }
        }
        __syncthreads();
    }
#undef STAGE_LOAD

    // --- epilogue: fragments -> global fp32 ---
    const int r0 = m0 + wm * 64 + (lane >> 2);
    const int c0 = n0 + wn * 32 + (lane & 3) * 2;
#pragma unroll
    for (int i = 0; i < 4; i++) {
#pragma unroll
        for (int j = 0; j < 4; j++) {
            float v0 = acc[i][j][0], v1 = acc[i][j][1];
            float v2 = acc[i][j][2], v3 = acc[i][j][3];
            if (do_sig) {
                v0 = __fdividef(1.f, 1.f + __expf(-v0));
                v1 = __fdividef(1.f, 1.f + __expf(-v1));
                v2 = __fdividef(1.f, 1.f + __expf(-v2));
                v3 = __fdividef(1.f, 1.f + __expf(-v3));
            }
            float* p = O + (size_t)(r0 + i * 16) * CC + c0 + j * 8;
            *(float2*)p              = make_float2(v0, v1);
            *(float2*)(p + 8 * CC)   = make_float2(v2, v3);
        }
    }
}

__global__ __launch_bounds__(256)
void gemm_kvr_mma()
{
    const int w     = blockIdx.x >> 1;        // 0:k 1:v 2:r
    const int ntile = blockIdx.x & 1;
    float* O = (w == 0) ? g_k : (w == 1) ? g_v : g_sr;
    gemm_mma_body(g_xhi, g_xlo, w, O, blockIdx.y * 128, ntile * 128, w == 2);
}

__global__ __launch_bounds__(256)
void gemm_out_mma(float* __restrict__ out)
{
    gemm_mma_body(g_zhi, g_zlo, 3, out, blockIdx.y * 128, (blockIdx.x & 1) * 128, 0);
}

// ---------------------------------------------------------------------------
// WKV pass 1: per (b, chunk) state recurrence from identity; 2 chains/thread.
// ---------------------------------------------------------------------------
__global__ __launch_bounds__(256)
void wkv_pass1_kernel(const float* __restrict__ decay)
{
    const int c  = threadIdx.x;
    const int j0 = blockIdx.x * 2;
    const int b  = blockIdx.y;
    const float w = decay[c] * INV_T;
    float p0 = 0.f, q0 = 0.f, o0 = -1e38f;
    float p1 = 0.f, q1 = 0.f, o1 = -1e38f;
    int idx0 = (b * TT + j0 * LCH) * CC + c;
    int idx1 = idx0 + LCH * CC;
#pragma unroll 4
    for (int t = 0; t < LCH; t++, idx0 += CC, idx1 += CC) {
        float k0 = g_k[idx0], v0 = g_v[idx0];
        float k1 = g_k[idx1], v1 = g_v[idx1];
        float n0 = fmaxf(w + o0, k0);
        float n1 = fmaxf(w + o1, k1);
        float a0 = __expf(w + o0 - n0), b0 = __expf(k0 - n0);
        float a1 = __expf(w + o1 - n1), b1 = __expf(k1 - n1);
        p0 = a0 * p0 + b0 * v0;  q0 = a0 * q0 + b0;  o0 = n0;
        p1 = a1 * p1 + b1 * v1;  q1 = a1 * q1 + b1;  o1 = n1;
    }
    int s0 = (b * NC + j0) * CC + c;
    g_rp[s0] = p0; g_rq[s0] = q0; g_ro[s0] = o0;
    int s1 = s0 + CC;
    g_rp[s1] = p1; g_rq[s1] = q1; g_ro[s1] = o1;
}

// ---------------------------------------------------------------------------
// WKV pass 2: sequential combine across chunk summaries per (b,c), batched 8.
// ---------------------------------------------------------------------------
__global__ __launch_bounds__(256)
void wkv_pass2_kernel(const float* __restrict__ decay)
{
    const int c = threadIdx.x;
    const int b = blockIdx.x;
    const float Lw = decay[c] * INV_T * (float)LCH;
    float p = 0.f, q = 0.f, o = -1e38f;
    for (int j0 = 0; j0 < NC; j0 += 8) {
        float rp8[8], rq8[8], ro8[8];
#pragma unroll
        for (int u = 0; u < 8; u++) {
            const int s = (b * NC + j0 + u) * CC + c;
            rp8[u] = g_rp[s]; rq8[u] = g_rq[s]; ro8[u] = g_ro[s];
        }
#pragma unroll
        for (int u = 0; u < 8; u++) {
            const int s = (b * NC + j0 + u) * CC + c;
            g_pp[s] = p; g_pq[s] = q; g_po[s] = o;
            float so = o + Lw;
            float no = fmaxf(so, ro8[u]);
            float ea = __expf(so - no);
            float eb = __expf(ro8[u] - no);
            p = ea * p + eb * rp8[u];
            q = ea * q + eb * rq8[u];
            o = no;
        }
    }
}

// ---------------------------------------------------------------------------
// WKV pass 3: replay chunk, fuse LayerNorm + sigmoid gate; write z as
// bf16 hi/lo (GEMM-ready).  LN reduction batched over 8 timesteps.
// ---------------------------------------------------------------------------
__global__ __launch_bounds__(256)
void wkv_pass3_kernel(const float* __restrict__ decay,
                      const float* __restrict__ first,
                      const float* __restrict__ ln_w,
                      const float* __restrict__ ln_b)
{
    __shared__ float sh_s [8][8];   // [t-sub][warp]
    __shared__ float sh_s2[8][8];
    const int c = threadIdx.x;
    const int j = blockIdx.x;
    const int b = blockIdx.y;
    const int wid  = c >> 5;
    const int lane = c & 31;

    const float w = decay[c] * INV_T;
    const float u = first[c] * INV_T;
    const float lw = ln_w[c], lb = ln_b[c];

    const int s = (b * NC + j) * CC + c;
    float p = g_pp[s], q = g_pq[s], o = g_po[s];

    int idx = (b * TT + j * LCH) * CC + c;
    for (int tb = 0; tb < LCH; tb += 8) {
        float yb[8];
        int idx2 = idx;
#pragma unroll
        for (int tt = 0; tt < 8; tt++, idx += CC) {
            float kt = g_k[idx], vt = g_v[idx];

            float no = fmaxf(o, u + kt);
            float ea = __expf(o - no);
            float eb = __expf(u + kt - no);
            float y  = __fdividef(ea * p + eb * vt, ea * q + eb);
            yb[tt] = y;

            float no2 = fmaxf(w + o, kt);
            float e2  = __expf(w + o - no2);
            float e3  = __expf(kt - no2);
            p = e2 * p + e3 * vt;
            q = e2 * q + e3;
            o = no2;

            float sv = y, sv2 = y * y;
#pragma unroll
            for (int off = 16; off; off >>= 1) {
                sv  += __shfl_xor_sync(0xffffffffu, sv,  off);
                sv2 += __shfl_xor_sync(0xffffffffu, sv2, off);
            }
            if (lane == 0) { sh_s[tt][wid] = sv; sh_s2[tt][wid] = sv2; }
        }
        __syncthreads();
#pragma unroll
        for (int tt = 0; tt < 8; tt++, idx2 += CC) {
            float mean = 0.f, msq = 0.f;
#pragma unroll
            for (int i = 0; i < 8; i++) { mean += sh_s[tt][i]; msq += sh_s2[tt][i]; }
            mean *= INV_C;
            float var = msq * INV_C - mean * mean;
            float inv = rsqrtf(var + 1e-5f);
            float z = (yb[tt] - mean) * inv * lw + lb;
            float zz = z * g_sr[idx2];
            __nv_bfloat16 zh = __float2bfloat16_rn(zz);
            __nv_bfloat16 zl = __float2bfloat16_rn(zz - __bfloat162float(zh));
            g_zhi[idx2] = zh;
            g_zlo[idx2] = zl;
        }
        __syncthreads();
    }
}

// ---------------------------------------------------------------------------
extern "C" void kernel_launch(void* const* d_in, const int* in_sizes, int n_in,
                              void* d_out, int out_size)
{
    const float* x     = (const float*)d_in[0];
    const float* Wk    = (const float*)d_in[1];
    const float* Wv    = (const float*)d_in[2];
    const float* Wr    = (const float*)d_in[3];
    const float* Wo    = (const float*)d_in[4];
    const float* decay = (const float*)d_in[5];
    const float* first = (const float*)d_in[6];
    const float* ln_w  = (const float*)d_in[7];
    const float* ln_b  = (const float*)d_in[8];
    float* out = (float*)d_out;

    // host-side attribute set (not a stream op; legal during capture)
    cudaFuncSetAttribute(gemm_kvr_mma, cudaFuncAttributeMaxDynamicSharedMemorySize, SMEM_BYTES);
    cudaFuncSetAttribute(gemm_out_mma, cudaFuncAttributeMaxDynamicSharedMemorySize, SMEM_BYTES);

    const int MT = (BB * TT) / 128;   // 256 m-tiles

    prep_w_kernel<<<512, 256>>>(Wk, Wv, Wr, Wo);
    prep_x_kernel<<<NTOT / 512, 256>>>(x);
    gemm_kvr_mma<<<dim3(6, MT), 256, SMEM_BYTES>>>();
    wkv_pass1_kernel<<<dim3(NC / 2, BB), 256>>>(decay);
    wkv_pass2_kernel<<<BB, 256>>>(decay);
    wkv_pass3_kernel<<<dim3(NC, BB), 256>>>(decay, first, ln_w, ln_b);
    gemm_out_mma<<<dim3(2, MT), 256, SMEM_BYTES>>>(out);
}

// round 15
// speedup vs baseline: 1.1860x; 1.1834x over previous
#include <cuda_runtime.h>
#include <cuda_bf16.h>
#include <cuda_fp16.h>
#include <cstdint>

// Problem dims (fixed by the reference)
#define BB   8
#define TT   4096
#define CC   256
#define NC   128          // chunks along T for the parallel WKV scan
#define LCH  (TT / NC)    // 32 steps per chunk
#define INV_T (1.0f / 4096.0f)
#define INV_C (1.0f / 256.0f)
#define NTOT (BB * TT * CC)

// ---------------- scratch (static __device__ — no allocations allowed) -----
__device__ float g_k [NTOT];
__device__ float g_v [NTOT];
__device__ float g_sr[NTOT];           // sigmoid(r) fp32
__device__ float g_rp[BB * NC * CC];
__device__ float g_rq[BB * NC * CC];
__device__ float g_ro[BB * NC * CC];
__device__ float g_pp[BB * NC * CC];
__device__ float g_pq[BB * NC * CC];
__device__ float g_po[BB * NC * CC];

// bf16 hi/lo split activations (A operand for the kvr GEMM)
__device__ __align__(16) __nv_bfloat16 g_xhi[NTOT];
__device__ __align__(16) __nv_bfloat16 g_xlo[NTOT];
// fp16 gated activation z = sigmoid(r)*LN(y)  (A operand for the out GEMM)
__device__ __align__(16) __half g_zh[NTOT];

// bf16 hi/lo split weights (k,v,r), [w][n=256][k=256], packed uint32 (2 bf16)
__device__ __align__(16) uint32_t g_whi[3 * 256 * 128];
__device__ __align__(16) uint32_t g_wlo[3 * 256 * 128];
// fp16 Wo, [n][k] packed uint32 (2 fp16)
__device__ __align__(16) uint32_t g_wo16[256 * 128];

// ---------------------------------------------------------------------------
// helpers
// ---------------------------------------------------------------------------
__device__ __forceinline__ uint32_t smem_u32(const void* p) {
    uint32_t a;
    asm("{ .reg .u64 t; cvta.to.shared.u64 t, %1; cvt.u32.u64 %0, t; }"
        : "=r"(a) : "l"(p));
    return a;
}

// split a pair of fp32 into packed bf16 hi and bf16 lo words
__device__ __forceinline__ void split2(float a, float b, uint32_t& h, uint32_t& l) {
    __nv_bfloat16 ha = __float2bfloat16_rn(a);
    __nv_bfloat16 hb = __float2bfloat16_rn(b);
    __nv_bfloat16 la = __float2bfloat16_rn(a - __bfloat162float(ha));
    __nv_bfloat16 lb = __float2bfloat16_rn(b - __bfloat162float(hb));
    h = ((uint32_t)__bfloat16_as_ushort(hb) << 16) | __bfloat16_as_ushort(ha);
    l = ((uint32_t)__bfloat16_as_ushort(lb) << 16) | __bfloat16_as_ushort(la);
}

__device__ __forceinline__ void ldmx4(uint32_t* r, uint32_t addr) {
    asm volatile("ldmatrix.sync.aligned.m8n8.x4.shared.b16 {%0,%1,%2,%3}, [%4];"
                 : "=r"(r[0]), "=r"(r[1]), "=r"(r[2]), "=r"(r[3]) : "r"(addr));
}
__device__ __forceinline__ void ldmx2(uint32_t* r, uint32_t addr) {
    asm volatile("ldmatrix.sync.aligned.m8n8.x2.shared.b16 {%0,%1}, [%2];"
                 : "=r"(r[0]), "=r"(r[1]) : "r"(addr));
}
__device__ __forceinline__ void mma16816(float* d, const uint32_t* a, const uint32_t* b) {
    asm volatile(
        "mma.sync.aligned.m16n8k16.row.col.f32.bf16.bf16.f32 "
        "{%0,%1,%2,%3}, {%4,%5,%6,%7}, {%8,%9}, {%0,%1,%2,%3};"
        : "+f"(d[0]), "+f"(d[1]), "+f"(d[2]), "+f"(d[3])
        : "r"(a[0]), "r"(a[1]), "r"(a[2]), "r"(a[3]), "r"(b[0]), "r"(b[1]));
}
__device__ __forceinline__ void mma16816h(float* d, const uint32_t* a, const uint32_t* b) {
    asm volatile(
        "mma.sync.aligned.m16n8k16.row.col.f32.f16.f16.f32 "
        "{%0,%1,%2,%3}, {%4,%5,%6,%7}, {%8,%9}, {%0,%1,%2,%3};"
        : "+f"(d[0]), "+f"(d[1]), "+f"(d[2]), "+f"(d[3])
        : "r"(a[0]), "r"(a[1]), "r"(a[2]), "r"(a[3]), "r"(b[0]), "r"(b[1]));
}
__device__ __forceinline__ void cp16(uint32_t saddr, const void* g) {
    asm volatile("cp.async.cg.shared.global [%0], [%1], 16;"
                 :: "r"(saddr), "l"(g) : "memory");
}
__device__ __forceinline__ void cp_commit() {
    asm volatile("cp.async.commit_group;" ::: "memory");
}

// ---------------------------------------------------------------------------
// Weight prep: Wk/Wv/Wr -> bf16 hi/lo pairs; Wo -> fp16 pairs.
// ---------------------------------------------------------------------------
__global__ __launch_bounds__(256)
void prep_w_kernel(const float* __restrict__ Wk, const float* __restrict__ Wv,
                   const float* __restrict__ Wr, const float* __restrict__ Wo)
{
    int gid = blockIdx.x * 256 + threadIdx.x;    // 0 .. 131071 = 4*256*128
    int kp  = gid & 127;
    int n   = (gid >> 7) & 255;
    int w   = gid >> 15;
    if (w < 3) {
        const float* W = (w == 0) ? Wk : (w == 1) ? Wv : Wr;
        float2 v = *(const float2*)(W + n * 256 + kp * 2);
        uint32_t h, l;
        split2(v.x, v.y, h, l);
        g_whi[gid] = h;
        g_wlo[gid] = l;
    } else {
        float2 v = *(const float2*)(Wo + n * 256 + kp * 2);
        __half2 hv = __floats2half2_rn(v.x, v.y);
        g_wo16[n * 128 + kp] = *(uint32_t*)&hv;
    }
}

// x fp32 -> bf16 hi/lo (one pass, so GEMM staging is a pure async copy)
__global__ __launch_bounds__(256)
void prep_x_kernel(const float* __restrict__ x)
{
    int gid = blockIdx.x * 256 + threadIdx.x;   // < NTOT/2
    float2 v = *(const float2*)(x + (size_t)gid * 2);
    uint32_t h, l;
    split2(v.x, v.y, h, l);
    ((uint32_t*)g_xhi)[gid] = h;
    ((uint32_t*)g_xlo)[gid] = l;
}

// ---------------------------------------------------------------------------
// Split-bf16 tensor-core GEMM (NT): O[m,n] = sum_c A[m,c]*W[n,c].
// CTA tile 128x128, BK=32, 8 warps (2m x 4n), fp32 accum,
// 3 MMA terms: Ahi*Whi + Ahi*Wlo + Alo*Whi.  2-stage cp.async pipeline.
// ---------------------------------------------------------------------------
#define PITCH 80                 // smem row pitch: 64 B data + 16 B pad
#define TBYTES (128 * PITCH)     // 10240 per tile
#define STG    (4 * TBYTES)      // per stage: Ahi,Alo,Whi,Wlo
#define SMEM_BYTES (2 * STG)     // 81920

__global__ __launch_bounds__(256)
void gemm_kvr_mma()
{
    extern __shared__ __align__(16) unsigned char smem[];
    const uint32_t base = smem_u32(smem);

    const int w_sel = blockIdx.x >> 1;        // 0:k 1:v 2:r
    const int n0    = (blockIdx.x & 1) * 128;
    const int m0    = blockIdx.y * 128;
    float* O = (w_sel == 0) ? g_k : (w_sel == 1) ? g_v : g_sr;

    const int tid  = threadIdx.x;
    const int wid  = tid >> 5;
    const int lane = tid & 31;
    const int wm   = wid & 1;
    const int wn   = wid >> 1;

    const uint32_t aOff = (uint32_t)((wm * 64 + (lane & 15)) * PITCH + (lane >> 4) * 16);
    const uint32_t bOff = (uint32_t)((wn * 32 + (lane & 7)) * PITCH + ((lane >> 3) & 1) * 16);

    float acc[4][4][4];
#pragma unroll
    for (int i = 0; i < 4; i++)
#pragma unroll
        for (int j = 0; j < 4; j++)
#pragma unroll
            for (int e = 0; e < 4; e++) acc[i][j][e] = 0.f;

    const int arow  = tid >> 1;
    const int ahalf = tid & 1;

    const __nv_bfloat16* pAh = g_xhi + (size_t)(m0 + arow) * CC + ahalf * 16;
    const __nv_bfloat16* pAl = g_xlo + (size_t)(m0 + arow) * CC + ahalf * 16;
    const uint32_t* pWh = g_whi + (w_sel * 256 + n0 + arow) * 128 + ahalf * 8;
    const uint32_t* pWl = g_wlo + (w_sel * 256 + n0 + arow) * 128 + ahalf * 8;
    const uint32_t sOff = (uint32_t)(arow * PITCH + ahalf * 32);

#define STAGE_LOAD(kc, s) do { \
        uint32_t so = base + (s) * STG + sOff; \
        cp16(so,                    pAh + (kc) * 32); \
        cp16(so + 16,               pAh + (kc) * 32 + 8); \
        cp16(so + TBYTES,           pAl + (kc) * 32); \
        cp16(so + TBYTES + 16,      pAl + (kc) * 32 + 8); \
        cp16(so + 2 * TBYTES,       pWh + (kc) * 16); \
        cp16(so + 2 * TBYTES + 16,  pWh + (kc) * 16 + 4); \
        cp16(so + 3 * TBYTES,       pWl + (kc) * 16); \
        cp16(so + 3 * TBYTES + 16,  pWl + (kc) * 16 + 4); \
        cp_commit(); \
    } while (0)

    STAGE_LOAD(0, 0);

    for (int kc = 0; kc < 8; kc++) {
        if (kc < 7) STAGE_LOAD(kc + 1, (kc + 1) & 1);
        if (kc < 7) asm volatile("cp.async.wait_group 1;" ::: "memory");
        else        asm volatile("cp.async.wait_group 0;" ::: "memory");
        __syncthreads();

        const uint32_t sb   = base + (kc & 1) * STG;
        const uint32_t uAhi = sb;
        const uint32_t uAlo = sb + TBYTES;
        const uint32_t uWhi = sb + 2 * TBYTES;
        const uint32_t uWlo = sb + 3 * TBYTES;

#pragma unroll
        for (int kk = 0; kk < 2; kk++) {
            uint32_t bh[4][2], bl[4][2];
#pragma unroll
            for (int j = 0; j < 4; j++) {
                uint32_t off = bOff + (uint32_t)(j * 8 * PITCH + kk * 32);
                ldmx2(bh[j], uWhi + off);
                ldmx2(bl[j], uWlo + off);
            }
#pragma unroll
            for (int i = 0; i < 4; i++) {
                uint32_t off = aOff + (uint32_t)(i * 16 * PITCH + kk * 32);
                uint32_t ah[4], al[4];
                ldmx4(ah, uAhi + off);
                ldmx4(al, uAlo + off);
#pragma unroll
                for (int j = 0; j < 4; j++) {
                    mma16816(acc[i][j], ah, bh[j]);
                    mma16816(acc[i][j], ah, bl[j]);
                    mma16816(acc[i][j], al, bh[j]);
                }
            }
        }
        __syncthreads();
    }
#undef STAGE_LOAD

    const int r0 = m0 + wm * 64 + (lane >> 2);
    const int c0 = n0 + wn * 32 + (lane & 3) * 2;
    const int do_sig = (w_sel == 2);
#pragma unroll
    for (int i = 0; i < 4; i++) {
#pragma unroll
        for (int j = 0; j < 4; j++) {
            float v0 = acc[i][j][0], v1 = acc[i][j][1];
            float v2 = acc[i][j][2], v3 = acc[i][j][3];
            if (do_sig) {
                v0 = __fdividef(1.f, 1.f + __expf(-v0));
                v1 = __fdividef(1.f, 1.f + __expf(-v1));
                v2 = __fdividef(1.f, 1.f + __expf(-v2));
                v3 = __fdividef(1.f, 1.f + __expf(-v3));
            }
            float* p = O + (size_t)(r0 + i * 16) * CC + c0 + j * 8;
            *(float2*)p              = make_float2(v0, v1);
            *(float2*)(p + 8 * CC)   = make_float2(v2, v3);
        }
    }
}

// ---------------------------------------------------------------------------
// fp16 single-term GEMM for the output projection: out = z @ Wo^T.
// Same tiling; 1 MMA term; 2-stage cp.async (2 tiles/stage, 40 KB smem).
// ---------------------------------------------------------------------------
#define OSTG (2 * TBYTES)
#define OSMEM_BYTES (2 * OSTG)   // 40960

__global__ __launch_bounds__(256)
void gemm_out_mma(float* __restrict__ out)
{
    extern __shared__ __align__(16) unsigned char smem[];
    const uint32_t base = smem_u32(smem);

    const int n0 = (blockIdx.x & 1) * 128;
    const int m0 = blockIdx.y * 128;

    const int tid  = threadIdx.x;
    const int wid  = tid >> 5;
    const int lane = tid & 31;
    const int wm   = wid & 1;
    const int wn   = wid >> 1;

    const uint32_t aOff = (uint32_t)((wm * 64 + (lane & 15)) * PITCH + (lane >> 4) * 16);
    const uint32_t bOff = (uint32_t)((wn * 32 + (lane & 7)) * PITCH + ((lane >> 3) & 1) * 16);

    float acc[4][4][4];
#pragma unroll
    for (int i = 0; i < 4; i++)
#pragma unroll
        for (int j = 0; j < 4; j++)
#pragma unroll
            for (int e = 0; e < 4; e++) acc[i][j][e] = 0.f;

    const int arow  = tid >> 1;
    const int ahalf = tid & 1;

    const __half* pA = g_zh + (size_t)(m0 + arow) * CC + ahalf * 16;
    const uint32_t* pW = g_wo16 + (n0 + arow) * 128 + ahalf * 8;
    const uint32_t sOff = (uint32_t)(arow * PITCH + ahalf * 32);

#define OSTAGE_LOAD(kc, s) do { \
        uint32_t so = base + (s) * OSTG + sOff; \
        cp16(so,               pA + (kc) * 32); \
        cp16(so + 16,          pA + (kc) * 32 + 8); \
        cp16(so + TBYTES,      pW + (kc) * 16); \
        cp16(so + TBYTES + 16, pW + (kc) * 16 + 4); \
        cp_commit(); \
    } while (0)

    OSTAGE_LOAD(0, 0);

    for (int kc = 0; kc < 8; kc++) {
        if (kc < 7) OSTAGE_LOAD(kc + 1, (kc + 1) & 1);
        if (kc < 7) asm volatile("cp.async.wait_group 1;" ::: "memory");
        else        asm volatile("cp.async.wait_group 0;" ::: "memory");
        __syncthreads();

        const uint32_t sb = base + (kc & 1) * OSTG;
        const uint32_t uA = sb;
        const uint32_t uW = sb + TBYTES;

#pragma unroll
        for (int kk = 0; kk < 2; kk++) {
            uint32_t bh[4][2];
#pragma unroll
            for (int j = 0; j < 4; j++)
                ldmx2(bh[j], uW + bOff + (uint32_t)(j * 8 * PITCH + kk * 32));
#pragma unroll
            for (int i = 0; i < 4; i++) {
                uint32_t ah[4];
                ldmx4(ah, uA + aOff + (uint32_t)(i * 16 * PITCH + kk * 32));
#pragma unroll
                for (int j = 0; j < 4; j++)
                    mma16816h(acc[i][j], ah, bh[j]);
            }
        }
        __syncthreads();
    }
#undef OSTAGE_LOAD

    const int r0 = m0 + wm * 64 + (lane >> 2);
    const int c0 = n0 + wn * 32 + (lane & 3) * 2;
#pragma unroll
    for (int i = 0; i < 4; i++) {
#pragma unroll
        for (int j = 0; j < 4; j++) {
            float* p = out + (size_t)(r0 + i * 16) * CC + c0 + j * 8;
            *(float2*)p            = make_float2(acc[i][j][0], acc[i][j][1]);
            *(float2*)(p + 8 * CC) = make_float2(acc[i][j][2], acc[i][j][3]);
        }
    }
}

// ---------------------------------------------------------------------------
// WKV pass 1: per (b, chunk) state recurrence from identity; 2 chains/thread.
// ---------------------------------------------------------------------------
__global__ __launch_bounds__(256)
void wkv_pass1_kernel(const float* __restrict__ decay)
{
    const int c  = threadIdx.x;
    const int j0 = blockIdx.x * 2;
    const int b  = blockIdx.y;
    const float w = decay[c] * INV_T;
    float p0 = 0.f, q0 = 0.f, o0 = -1e38f;
    float p1 = 0.f, q1 = 0.f, o1 = -1e38f;
    int idx0 = (b * TT + j0 * LCH) * CC + c;
    int idx1 = idx0 + LCH * CC;
#pragma unroll 4
    for (int t = 0; t < LCH; t++, idx0 += CC, idx1 += CC) {
        float k0 = g_k[idx0], v0 = g_v[idx0];
        float k1 = g_k[idx1], v1 = g_v[idx1];
        float n0 = fmaxf(w + o0, k0);
        float n1 = fmaxf(w + o1, k1);
        float a0 = __expf(w + o0 - n0), b0 = __expf(k0 - n0);
        float a1 = __expf(w + o1 - n1), b1 = __expf(k1 - n1);
        p0 = a0 * p0 + b0 * v0;  q0 = a0 * q0 + b0;  o0 = n0;
        p1 = a1 * p1 + b1 * v1;  q1 = a1 * q1 + b1;  o1 = n1;
    }
    int s0 = (b * NC + j0) * CC + c;
    g_rp[s0] = p0; g_rq[s0] = q0; g_ro[s0] = o0;
    int s1 = s0 + CC;
    g_rp[s1] = p1; g_rq[s1] = q1; g_ro[s1] = o1;
}

// ---------------------------------------------------------------------------
// WKV pass 2: sequential combine across chunk summaries per (b,c), batched 16.
// ---------------------------------------------------------------------------
__global__ __launch_bounds__(256)
void wkv_pass2_kernel(const float* __restrict__ decay)
{
    const int c = threadIdx.x;
    const int b = blockIdx.x;
    const float Lw = decay[c] * INV_T * (float)LCH;
    float p = 0.f, q = 0.f, o = -1e38f;
    for (int j0 = 0; j0 < NC; j0 += 16) {
        float rp8[16], rq8[16], ro8[16];
#pragma unroll
        for (int u = 0; u < 16; u++) {
            const int s = (b * NC + j0 + u) * CC + c;
            rp8[u] = g_rp[s]; rq8[u] = g_rq[s]; ro8[u] = g_ro[s];
        }
#pragma unroll
        for (int u = 0; u < 16; u++) {
            const int s = (b * NC + j0 + u) * CC + c;
            g_pp[s] = p; g_pq[s] = q; g_po[s] = o;
            float so = o + Lw;
            float no = fmaxf(so, ro8[u]);
            float ea = __expf(so - no);
            float eb = __expf(ro8[u] - no);
            p = ea * p + eb * rp8[u];
            q = ea * q + eb * rq8[u];
            o = no;
        }
    }
}

// ---------------------------------------------------------------------------
// WKV pass 3: replay chunk, fuse LayerNorm + sigmoid gate; write z as fp16.
// LN reduction batched over 8 timesteps (one barrier pair per 8 steps).
// ---------------------------------------------------------------------------
__global__ __launch_bounds__(256)
void wkv_pass3_kernel(const float* __restrict__ decay,
                      const float* __restrict__ first,
                      const float* __restrict__ ln_w,
                      const float* __restrict__ ln_b)
{
    __shared__ float sh_s [8][8];   // [t-sub][warp]
    __shared__ float sh_s2[8][8];
    const int c = threadIdx.x;
    const int j = blockIdx.x;
    const int b = blockIdx.y;
    const int wid  = c >> 5;
    const int lane = c & 31;

    const float w = decay[c] * INV_T;
    const float u = first[c] * INV_T;
    const float lw = ln_w[c], lb = ln_b[c];

    const int s = (b * NC + j) * CC + c;
    float p = g_pp[s], q = g_pq[s], o = g_po[s];

    int idx = (b * TT + j * LCH) * CC + c;
    for (int tb = 0; tb < LCH; tb += 8) {
        float yb[8];
        int idx2 = idx;
#pragma unroll
        for (int tt = 0; tt < 8; tt++, idx += CC) {
            float kt = g_k[idx], vt = g_v[idx];

            float no = fmaxf(o, u + kt);
            float ea = __expf(o - no);
            float eb = __expf(u + kt - no);
            float y  = __fdividef(ea * p + eb * vt, ea * q + eb);
            yb[tt] = y;

            float no2 = fmaxf(w + o, kt);
            float e2  = __expf(w + o - no2);
            float e3  = __expf(kt - no2);
            p = e2 * p + e3 * vt;
            q = e2 * q + e3;
            o = no2;

            float sv = y, sv2 = y * y;
#pragma unroll
            for (int off = 16; off; off >>= 1) {
                sv  += __shfl_xor_sync(0xffffffffu, sv,  off);
                sv2 += __shfl_xor_sync(0xffffffffu, sv2, off);
            }
            if (lane == 0) { sh_s[tt][wid] = sv; sh_s2[tt][wid] = sv2; }
        }
        __syncthreads();
#pragma unroll
        for (int tt = 0; tt < 8; tt++, idx2 += CC) {
            float mean = 0.f, msq = 0.f;
#pragma unroll
            for (int i = 0; i < 8; i++) { mean += sh_s[tt][i]; msq += sh_s2[tt][i]; }
            mean *= INV_C;
            float var = msq * INV_C - mean * mean;
            float inv = rsqrtf(var + 1e-5f);
            float z = (yb[tt] - mean) * inv * lw + lb;
            g_zh[idx2] = __float2half_rn(z * g_sr[idx2]);
        }
        __syncthreads();
    }
}

// ---------------------------------------------------------------------------
extern "C" void kernel_launch(void* const* d_in, const int* in_sizes, int n_in,
                              void* d_out, int out_size)
{
    const float* x     = (const float*)d_in[0];
    const float* Wk    = (const float*)d_in[1];
    const float* Wv    = (const float*)d_in[2];
    const float* Wr    = (const float*)d_in[3];
    const float* Wo    = (const float*)d_in[4];
    const float* decay = (const float*)d_in[5];
    const float* first = (const float*)d_in[6];
    const float* ln_w  = (const float*)d_in[7];
    const float* ln_b  = (const float*)d_in[8];
    float* out = (float*)d_out;

    cudaFuncSetAttribute(gemm_kvr_mma, cudaFuncAttributeMaxDynamicSharedMemorySize, SMEM_BYTES);
    cudaFuncSetAttribute(gemm_out_mma, cudaFuncAttributeMaxDynamicSharedMemorySize, OSMEM_BYTES);

    const int MT = (BB * TT) / 128;   // 256 m-tiles

    prep_w_kernel<<<512, 256>>>(Wk, Wv, Wr, Wo);
    prep_x_kernel<<<NTOT / 512, 256>>>(x);
    gemm_kvr_mma<<<dim3(6, MT), 256, SMEM_BYTES>>>();
    wkv_pass1_kernel<<<dim3(NC / 2, BB), 256>>>(decay);
    wkv_pass2_kernel<<<BB, 256>>>(decay);
    wkv_pass3_kernel<<<dim3(NC, BB), 256>>>(decay, first, ln_w, ln_b);
    gemm_out_mma<<<dim3(2, MT), 256, OSMEM_BYTES>>>(out);
}

// round 16
// speedup vs baseline: 1.2022x; 1.0137x over previous
#include <cuda_runtime.h>
#include <cuda_bf16.h>
#include <cuda_fp16.h>
#include <cstdint>

// Problem dims (fixed by the reference)
#define BB   8
#define TT   4096
#define CC   256
#define NC   128          // chunks along T for the parallel WKV scan
#define LCH  (TT / NC)    // 32 steps per chunk
#define INV_T (1.0f / 4096.0f)
#define INV_C (1.0f / 256.0f)
#define NTOT (BB * TT * CC)

// ---------------- scratch (static __device__ — no allocations allowed) -----
__device__ float g_k [NTOT];
__device__ float g_v [NTOT];
__device__ float g_sr[NTOT];           // sigmoid(r) fp32
__device__ float g_rp[BB * NC * CC];
__device__ float g_rq[BB * NC * CC];
__device__ float g_ro[BB * NC * CC];
__device__ float g_pp[BB * NC * CC];
__device__ float g_pq[BB * NC * CC];
__device__ float g_po[BB * NC * CC];

// bf16 hi/lo split activations (A operand for the kvr GEMM)
__device__ __align__(16) __nv_bfloat16 g_xhi[NTOT];
__device__ __align__(16) __nv_bfloat16 g_xlo[NTOT];
// fp16 gated activation z = sigmoid(r)*LN(y)  (A operand for the out GEMM)
__device__ __align__(16) __half g_zh[NTOT];

// bf16 hi/lo split weights (k,v,r), [w][n=256][k=256], packed uint32 (2 bf16)
__device__ __align__(16) uint32_t g_whi[3 * 256 * 128];
__device__ __align__(16) uint32_t g_wlo[3 * 256 * 128];
// fp16 Wo, [n][k] packed uint32 (2 fp16)
__device__ __align__(16) uint32_t g_wo16[256 * 128];

// ---------------------------------------------------------------------------
// helpers
// ---------------------------------------------------------------------------
__device__ __forceinline__ uint32_t smem_u32(const void* p) {
    uint32_t a;
    asm("{ .reg .u64 t; cvta.to.shared.u64 t, %1; cvt.u32.u64 %0, t; }"
        : "=r"(a) : "l"(p));
    return a;
}

// split a pair of fp32 into packed bf16 hi and bf16 lo words
__device__ __forceinline__ void split2(float a, float b, uint32_t& h, uint32_t& l) {
    __nv_bfloat16 ha = __float2bfloat16_rn(a);
    __nv_bfloat16 hb = __float2bfloat16_rn(b);
    __nv_bfloat16 la = __float2bfloat16_rn(a - __bfloat162float(ha));
    __nv_bfloat16 lb = __float2bfloat16_rn(b - __bfloat162float(hb));
    h = ((uint32_t)__bfloat16_as_ushort(hb) << 16) | __bfloat16_as_ushort(ha);
    l = ((uint32_t)__bfloat16_as_ushort(lb) << 16) | __bfloat16_as_ushort(la);
}

__device__ __forceinline__ void ldmx4(uint32_t* r, uint32_t addr) {
    asm volatile("ldmatrix.sync.aligned.m8n8.x4.shared.b16 {%0,%1,%2,%3}, [%4];"
                 : "=r"(r[0]), "=r"(r[1]), "=r"(r[2]), "=r"(r[3]) : "r"(addr));
}
__device__ __forceinline__ void ldmx2(uint32_t* r, uint32_t addr) {
    asm volatile("ldmatrix.sync.aligned.m8n8.x2.shared.b16 {%0,%1}, [%2];"
                 : "=r"(r[0]), "=r"(r[1]) : "r"(addr));
}
__device__ __forceinline__ void mma16816(float* d, const uint32_t* a, const uint32_t* b) {
    asm volatile(
        "mma.sync.aligned.m16n8k16.row.col.f32.bf16.bf16.f32 "
        "{%0,%1,%2,%3}, {%4,%5,%6,%7}, {%8,%9}, {%0,%1,%2,%3};"
        : "+f"(d[0]), "+f"(d[1]), "+f"(d[2]), "+f"(d[3])
        : "r"(a[0]), "r"(a[1]), "r"(a[2]), "r"(a[3]), "r"(b[0]), "r"(b[1]));
}
__device__ __forceinline__ void mma16816h(float* d, const uint32_t* a, const uint32_t* b) {
    asm volatile(
        "mma.sync.aligned.m16n8k16.row.col.f32.f16.f16.f32 "
        "{%0,%1,%2,%3}, {%4,%5,%6,%7}, {%8,%9}, {%0,%1,%2,%3};"
        : "+f"(d[0]), "+f"(d[1]), "+f"(d[2]), "+f"(d[3])
        : "r"(a[0]), "r"(a[1]), "r"(a[2]), "r"(a[3]), "r"(b[0]), "r"(b[1]));
}
__device__ __forceinline__ void cp16(uint32_t saddr, const void* g) {
    asm volatile("cp.async.cg.shared.global [%0], [%1], 16;"
                 :: "r"(saddr), "l"(g) : "memory");
}
__device__ __forceinline__ void cp_commit() {
    asm volatile("cp.async.commit_group;" ::: "memory");
}

// ---------------------------------------------------------------------------
// Weight prep: Wk/Wv/Wr -> bf16 hi/lo pairs; Wo -> fp16 pairs.
// ---------------------------------------------------------------------------
__global__ __launch_bounds__(256)
void prep_w_kernel(const float* __restrict__ Wk, const float* __restrict__ Wv,
                   const float* __restrict__ Wr, const float* __restrict__ Wo)
{
    int gid = blockIdx.x * 256 + threadIdx.x;    // 0 .. 131071 = 4*256*128
    int kp  = gid & 127;
    int n   = (gid >> 7) & 255;
    int w   = gid >> 15;
    if (w < 3) {
        const float* W = (w == 0) ? Wk : (w == 1) ? Wv : Wr;
        float2 v = *(const float2*)(W + n * 256 + kp * 2);
        uint32_t h, l;
        split2(v.x, v.y, h, l);
        g_whi[gid] = h;
        g_wlo[gid] = l;
    } else {
        float2 v = *(const float2*)(Wo + n * 256 + kp * 2);
        __half2 hv = __floats2half2_rn(v.x, v.y);
        g_wo16[n * 128 + kp] = *(uint32_t*)&hv;
    }
}

// x fp32 -> bf16 hi/lo (one pass, so GEMM staging is a pure async copy)
__global__ __launch_bounds__(256)
void prep_x_kernel(const float* __restrict__ x)
{
    int gid = blockIdx.x * 256 + threadIdx.x;   // < NTOT/2
    float2 v = *(const float2*)(x + (size_t)gid * 2);
    uint32_t h, l;
    split2(v.x, v.y, h, l);
    ((uint32_t*)g_xhi)[gid] = h;
    ((uint32_t*)g_xlo)[gid] = l;
}

// ---------------------------------------------------------------------------
// Split-bf16 tensor-core GEMM (NT): O[m,n] = sum_c A[m,c]*W[n,c].
// CTA tile 128x128, BK=32, 8 warps (2m x 4n), fp32 accum,
// 3 MMA terms: Ahi*Whi + Ahi*Wlo + Alo*Whi.  2-stage cp.async pipeline.
// ---------------------------------------------------------------------------
#define PITCH 80                 // smem row pitch: 64 B data + 16 B pad
#define TBYTES (128 * PITCH)     // 10240 per tile
#define STG    (4 * TBYTES)      // per stage: Ahi,Alo,Whi,Wlo
#define SMEM_BYTES (2 * STG)     // 81920

__global__ __launch_bounds__(256)
void gemm_kvr_mma()
{
    extern __shared__ __align__(16) unsigned char smem[];
    const uint32_t base = smem_u32(smem);

    const int w_sel = blockIdx.x >> 1;        // 0:k 1:v 2:r
    const int n0    = (blockIdx.x & 1) * 128;
    const int m0    = blockIdx.y * 128;
    float* O = (w_sel == 0) ? g_k : (w_sel == 1) ? g_v : g_sr;

    const int tid  = threadIdx.x;
    const int wid  = tid >> 5;
    const int lane = tid & 31;
    const int wm   = wid & 1;
    const int wn   = wid >> 1;

    const uint32_t aOff = (uint32_t)((wm * 64 + (lane & 15)) * PITCH + (lane >> 4) * 16);
    const uint32_t bOff = (uint32_t)((wn * 32 + (lane & 7)) * PITCH + ((lane >> 3) & 1) * 16);

    float acc[4][4][4];
#pragma unroll
    for (int i = 0; i < 4; i++)
#pragma unroll
        for (int j = 0; j < 4; j++)
#pragma unroll
            for (int e = 0; e < 4; e++) acc[i][j][e] = 0.f;

    const int arow  = tid >> 1;
    const int ahalf = tid & 1;

    const __nv_bfloat16* pAh = g_xhi + (size_t)(m0 + arow) * CC + ahalf * 16;
    const __nv_bfloat16* pAl = g_xlo + (size_t)(m0 + arow) * CC + ahalf * 16;
    const uint32_t* pWh = g_whi + (w_sel * 256 + n0 + arow) * 128 + ahalf * 8;
    const uint32_t* pWl = g_wlo + (w_sel * 256 + n0 + arow) * 128 + ahalf * 8;
    const uint32_t sOff = (uint32_t)(arow * PITCH + ahalf * 32);

#define STAGE_LOAD(kc, s) do { \
        uint32_t so = base + (s) * STG + sOff; \
        cp16(so,                    pAh + (kc) * 32); \
        cp16(so + 16,               pAh + (kc) * 32 + 8); \
        cp16(so + TBYTES,           pAl + (kc) * 32); \
        cp16(so + TBYTES + 16,      pAl + (kc) * 32 + 8); \
        cp16(so + 2 * TBYTES,       pWh + (kc) * 16); \
        cp16(so + 2 * TBYTES + 16,  pWh + (kc) * 16 + 4); \
        cp16(so + 3 * TBYTES,       pWl + (kc) * 16); \
        cp16(so + 3 * TBYTES + 16,  pWl + (kc) * 16 + 4); \
        cp_commit(); \
    } while (0)

    STAGE_LOAD(0, 0);

    for (int kc = 0; kc < 8; kc++) {
        if (kc < 7) STAGE_LOAD(kc + 1, (kc + 1) & 1);
        if (kc < 7) asm volatile("cp.async.wait_group 1;" ::: "memory");
        else        asm volatile("cp.async.wait_group 0;" ::: "memory");
        __syncthreads();

        const uint32_t sb   = base + (kc & 1) * STG;
        const uint32_t uAhi = sb;
        const uint32_t uAlo = sb + TBYTES;
        const uint32_t uWhi = sb + 2 * TBYTES;
        const uint32_t uWlo = sb + 3 * TBYTES;

#pragma unroll
        for (int kk = 0; kk < 2; kk++) {
            uint32_t bh[4][2], bl[4][2];
#pragma unroll
            for (int j = 0; j < 4; j++) {
                uint32_t off = bOff + (uint32_t)(j * 8 * PITCH + kk * 32);
                ldmx2(bh[j], uWhi + off);
                ldmx2(bl[j], uWlo + off);
            }
#pragma unroll
            for (int i = 0; i < 4; i++) {
                uint32_t off = aOff + (uint32_t)(i * 16 * PITCH + kk * 32);
                uint32_t ah[4], al[4];
                ldmx4(ah, uAhi + off);
                ldmx4(al, uAlo + off);
#pragma unroll
                for (int j = 0; j < 4; j++) {
                    mma16816(acc[i][j], ah, bh[j]);
                    mma16816(acc[i][j], ah, bl[j]);
                    mma16816(acc[i][j], al, bh[j]);
                }
            }
        }
        __syncthreads();
    }
#undef STAGE_LOAD

    const int r0 = m0 + wm * 64 + (lane >> 2);
    const int c0 = n0 + wn * 32 + (lane & 3) * 2;
    const int do_sig = (w_sel == 2);
#pragma unroll
    for (int i = 0; i < 4; i++) {
#pragma unroll
        for (int j = 0; j < 4; j++) {
            float v0 = acc[i][j][0], v1 = acc[i][j][1];
            float v2 = acc[i][j][2], v3 = acc[i][j][3];
            if (do_sig) {
                v0 = __fdividef(1.f, 1.f + __expf(-v0));
                v1 = __fdividef(1.f, 1.f + __expf(-v1));
                v2 = __fdividef(1.f, 1.f + __expf(-v2));
                v3 = __fdividef(1.f, 1.f + __expf(-v3));
            }
            float* p = O + (size_t)(r0 + i * 16) * CC + c0 + j * 8;
            *(float2*)p              = make_float2(v0, v1);
            *(float2*)(p + 8 * CC)   = make_float2(v2, v3);
        }
    }
}

// ---------------------------------------------------------------------------
// fp16 single-term GEMM for the output projection: out = z @ Wo^T.
// Same tiling; 1 MMA term; 2-stage cp.async (2 tiles/stage, 40 KB smem).
// ---------------------------------------------------------------------------
#define OSTG (2 * TBYTES)
#define OSMEM_BYTES (2 * OSTG)   // 40960

__global__ __launch_bounds__(256)
void gemm_out_mma(float* __restrict__ out)
{
    extern __shared__ __align__(16) unsigned char smem[];
    const uint32_t base = smem_u32(smem);

    const int n0 = (blockIdx.x & 1) * 128;
    const int m0 = blockIdx.y * 128;

    const int tid  = threadIdx.x;
    const int wid  = tid >> 5;
    const int lane = tid & 31;
    const int wm   = wid & 1;
    const int wn   = wid >> 1;

    const uint32_t aOff = (uint32_t)((wm * 64 + (lane & 15)) * PITCH + (lane >> 4) * 16);
    const uint32_t bOff = (uint32_t)((wn * 32 + (lane & 7)) * PITCH + ((lane >> 3) & 1) * 16);

    float acc[4][4][4];
#pragma unroll
    for (int i = 0; i < 4; i++)
#pragma unroll
        for (int j = 0; j < 4; j++)
#pragma unroll
            for (int e = 0; e < 4; e++) acc[i][j][e] = 0.f;

    const int arow  = tid >> 1;
    const int ahalf = tid & 1;

    const __half* pA = g_zh + (size_t)(m0 + arow) * CC + ahalf * 16;
    const uint32_t* pW = g_wo16 + (n0 + arow) * 128 + ahalf * 8;
    const uint32_t sOff = (uint32_t)(arow * PITCH + ahalf * 32);

#define OSTAGE_LOAD(kc, s) do { \
        uint32_t so = base + (s) * OSTG + sOff; \
        cp16(so,               pA + (kc) * 32); \
        cp16(so + 16,          pA + (kc) * 32 + 8); \
        cp16(so + TBYTES,      pW + (kc) * 16); \
        cp16(so + TBYTES + 16, pW + (kc) * 16 + 4); \
        cp_commit(); \
    } while (0)

    OSTAGE_LOAD(0, 0);

    for (int kc = 0; kc < 8; kc++) {
        if (kc < 7) OSTAGE_LOAD(kc + 1, (kc + 1) & 1);
        if (kc < 7) asm volatile("cp.async.wait_group 1;" ::: "memory");
        else        asm volatile("cp.async.wait_group 0;" ::: "memory");
        __syncthreads();

        const uint32_t sb = base + (kc & 1) * OSTG;
        const uint32_t uA = sb;
        const uint32_t uW = sb + TBYTES;

#pragma unroll
        for (int kk = 0; kk < 2; kk++) {
            uint32_t bh[4][2];
#pragma unroll
            for (int j = 0; j < 4; j++)
                ldmx2(bh[j], uW + bOff + (uint32_t)(j * 8 * PITCH + kk * 32));
#pragma unroll
            for (int i = 0; i < 4; i++) {
                uint32_t ah[4];
                ldmx4(ah, uA + aOff + (uint32_t)(i * 16 * PITCH + kk * 32));
#pragma unroll
                for (int j = 0; j < 4; j++)
                    mma16816h(acc[i][j], ah, bh[j]);
            }
        }
        __syncthreads();
    }
#undef OSTAGE_LOAD

    const int r0 = m0 + wm * 64 + (lane >> 2);
    const int c0 = n0 + wn * 32 + (lane & 3) * 2;
#pragma unroll
    for (int i = 0; i < 4; i++) {
#pragma unroll
        for (int j = 0; j < 4; j++) {
            float* p = out + (size_t)(r0 + i * 16) * CC + c0 + j * 8;
            *(float2*)p            = make_float2(acc[i][j][0], acc[i][j][1]);
            *(float2*)(p + 8 * CC) = make_float2(acc[i][j][2], acc[i][j][3]);
        }
    }
}

// ---------------------------------------------------------------------------
// WKV pass 1: per (b, chunk) state recurrence from identity; 2 chains/thread.
// ---------------------------------------------------------------------------
__global__ __launch_bounds__(256)
void wkv_pass1_kernel(const float* __restrict__ decay)
{
    const int c  = threadIdx.x;
    const int j0 = blockIdx.x * 2;
    const int b  = blockIdx.y;
    const float w = decay[c] * INV_T;
    float p0 = 0.f, q0 = 0.f, o0 = -1e38f;
    float p1 = 0.f, q1 = 0.f, o1 = -1e38f;
    int idx0 = (b * TT + j0 * LCH) * CC + c;
    int idx1 = idx0 + LCH * CC;
#pragma unroll 4
    for (int t = 0; t < LCH; t++, idx0 += CC, idx1 += CC) {
        float k0 = g_k[idx0], v0 = g_v[idx0];
        float k1 = g_k[idx1], v1 = g_v[idx1];
        float n0 = fmaxf(w + o0, k0);
        float n1 = fmaxf(w + o1, k1);
        float a0 = __expf(w + o0 - n0), b0 = __expf(k0 - n0);
        float a1 = __expf(w + o1 - n1), b1 = __expf(k1 - n1);
        p0 = a0 * p0 + b0 * v0;  q0 = a0 * q0 + b0;  o0 = n0;
        p1 = a1 * p1 + b1 * v1;  q1 = a1 * q1 + b1;  o1 = n1;
    }
    int s0 = (b * NC + j0) * CC + c;
    g_rp[s0] = p0; g_rq[s0] = q0; g_ro[s0] = o0;
    int s1 = s0 + CC;
    g_rp[s1] = p1; g_rq[s1] = q1; g_ro[s1] = o1;
}

// ---------------------------------------------------------------------------
// WKV pass 2: sequential combine across chunk summaries per (b,c), batched 16.
// ---------------------------------------------------------------------------
__global__ __launch_bounds__(256)
void wkv_pass2_kernel(const float* __restrict__ decay)
{
    const int c = threadIdx.x;
    const int b = blockIdx.x;
    const float Lw = decay[c] * INV_T * (float)LCH;
    float p = 0.f, q = 0.f, o = -1e38f;
    for (int j0 = 0; j0 < NC; j0 += 16) {
        float rp8[16], rq8[16], ro8[16];
#pragma unroll
        for (int u = 0; u < 16; u++) {
            const int s = (b * NC + j0 + u) * CC + c;
            rp8[u] = g_rp[s]; rq8[u] = g_rq[s]; ro8[u] = g_ro[s];
        }
#pragma unroll
        for (int u = 0; u < 16; u++) {
            const int s = (b * NC + j0 + u) * CC + c;
            g_pp[s] = p; g_pq[s] = q; g_po[s] = o;
            float so = o + Lw;
            float no = fmaxf(so, ro8[u]);
            float ea = __expf(so - no);
            float eb = __expf(ro8[u] - no);
            p = ea * p + eb * rp8[u];
            q = ea * q + eb * rq8[u];
            o = no;
        }
    }
}

// ---------------------------------------------------------------------------
// WKV pass 3: replay chunk, fuse LayerNorm + sigmoid gate; write z as fp16.
// LN reduction batched over 8 timesteps (one barrier pair per 8 steps).
// ---------------------------------------------------------------------------
__global__ __launch_bounds__(256)
void wkv_pass3_kernel(const float* __restrict__ decay,
                      const float* __restrict__ first,
                      const float* __restrict__ ln_w,
                      const float* __restrict__ ln_b)
{
    __shared__ float sh_s [8][8];   // [t-sub][warp]
    __shared__ float sh_s2[8][8];
    const int c = threadIdx.x;
    const int j = blockIdx.x;
    const int b = blockIdx.y;
    const int wid  = c >> 5;
    const int lane = c & 31;

    const float w = decay[c] * INV_T;
    const float u = first[c] * INV_T;
    const float lw = ln_w[c], lb = ln_b[c];

    const int s = (b * NC + j) * CC + c;
    float p = g_pp[s], q = g_pq[s], o = g_po[s];

    int idx = (b * TT + j * LCH) * CC + c;
    for (int tb = 0; tb < LCH; tb += 8) {
        float yb[8];
        int idx2 = idx;
#pragma unroll
        for (int tt = 0; tt < 8; tt++, idx += CC) {
            float kt = g_k[idx], vt = g_v[idx];

            float no = fmaxf(o, u + kt);
            float ea = __expf(o - no);
            float eb = __expf(u + kt - no);
            float y  = __fdividef(ea * p + eb * vt, ea * q + eb);
            yb[tt] = y;

            float no2 = fmaxf(w + o, kt);
            float e2  = __expf(w + o - no2);
            float e3  = __expf(kt - no2);
            p = e2 * p + e3 * vt;
            q = e2 * q + e3;
            o = no2;

            float sv = y, sv2 = y * y;
#pragma unroll
            for (int off = 16; off; off >>= 1) {
                sv  += __shfl_xor_sync(0xffffffffu, sv,  off);
                sv2 += __shfl_xor_sync(0xffffffffu, sv2, off);
            }
            if (lane == 0) { sh_s[tt][wid] = sv; sh_s2[tt][wid] = sv2; }
        }
        __syncthreads();
#pragma unroll
        for (int tt = 0; tt < 8; tt++, idx2 += CC) {
            float mean = 0.f, msq = 0.f;
#pragma unroll
            for (int i = 0; i < 8; i++) { mean += sh_s[tt][i]; msq += sh_s2[tt][i]; }
            mean *= INV_C;
            float var = msq * INV_C - mean * mean;
            float inv = rsqrtf(var + 1e-5f);
            float z = (yb[tt] - mean) * inv * lw + lb;
            g_zh[idx2] = __float2half_rn(z * g_sr[idx2]);
        }
        __syncthreads();
    }
}

// ---------------------------------------------------------------------------
extern "C" void kernel_launch(void* const* d_in, const int* in_sizes, int n_in,
                              void* d_out, int out_size)
{
    const float* x     = (const float*)d_in[0];
    const float* Wk    = (const float*)d_in[1];
    const float* Wv    = (const float*)d_in[2];
    const float* Wr    = (const float*)d_in[3];
    const float* Wo    = (const float*)d_in[4];
    const float* decay = (const float*)d_in[5];
    const float* first = (const float*)d_in[6];
    const float* ln_w  = (const float*)d_in[7];
    const float* ln_b  = (const float*)d_in[8];
    float* out = (float*)d_out;

    cudaFuncSetAttribute(gemm_kvr_mma, cudaFuncAttributeMaxDynamicSharedMemorySize, SMEM_BYTES);
    cudaFuncSetAttribute(gemm_out_mma, cudaFuncAttributeMaxDynamicSharedMemorySize, OSMEM_BYTES);

    const int MT = (BB * TT) / 128;   // 256 m-tiles

    prep_w_kernel<<<512, 256>>>(Wk, Wv, Wr, Wo);
    prep_x_kernel<<<NTOT / 512, 256>>>(x);
    gemm_kvr_mma<<<dim3(6, MT), 256, SMEM_BYTES>>>();
    wkv_pass1_kernel<<<dim3(NC / 2, BB), 256>>>(decay);
    wkv_pass2_kernel<<<BB, 256>>>(decay);
    wkv_pass3_kernel<<<dim3(NC, BB), 256>>>(decay, first, ln_w, ln_b);
    gemm_out_mma<<<dim3(2, MT), 256, OSMEM_BYTES>>>(out);
}